// round 16
// baseline (speedup 1.0000x reference)
#include <cuda_runtime.h>
#include <cstdint>

// ---------------- problem constants ----------------
#define BB      64
#define CC      256
#define HWX     3136        // 56*56
#define G       4
#define NCH     64
#define MTOT    (BB*HWX)
#define EPSV    1e-5f
#define NS_T    5
#define NSP     72          // ns matrix pitch (conflict-free frag loads)

// cov tiling: 64-sample tiles (49/image exact), 2-stage, 4 CTAs/SM (R15)
#define CTC     64
#define CCH     49           // chunks per image
#define CTILESC (BB*CCH)     // 3136 per group
#define NBLKC   148          // cov blocks per group (grid 592 = 4/SM)
#define CPC     68           // pitch%32==4 -> conflict-free frag loads
#define RPITCH  33           // reduction-area pitch

// whiten tiling: 64-sample tiles (49/image exact), 2-stage, 3 CTAs/SM
#define WTC     64
#define WCH     49
#define WTILES2 (BB*WCH)     // 3136 per group
#define NBLKW   111          // whiten blocks per group (grid 444 = 3/SM)
#define WP2     72           // pitch%32==8 -> B-read banks 8*t4+g distinct

// ---------------- device scratch ----------------
__device__ float g_S2[G][NCH][NCH];
__device__ float g_sum[G][NCH];
__device__ float g_wm[G][NCH][NCH];   // [g][c][d], weight+sqrt(rTr) folded in
__device__ float g_beta[G][NCH];

// ---------------- helpers ----------------
__device__ __forceinline__ uint32_t tf32r(float f) {
    uint32_t r; asm("cvt.rn.tf32.f32 %0, %1;" : "=r"(r) : "f"(f)); return r;
}
__device__ __forceinline__ uint32_t smem_u32(const void* p) {
    uint32_t a;
    asm("{ .reg .u64 t; cvta.to.shared.u64 t, %1; cvt.u32.u64 %0, t; }"
        : "=r"(a) : "l"(p));
    return a;
}
__device__ __forceinline__ void mma8(float* d, const uint32_t* a,
                                     uint32_t b0, uint32_t b1) {
    asm volatile("mma.sync.aligned.m16n8k8.row.col.f32.tf32.tf32.f32 "
                 "{%0,%1,%2,%3}, {%4,%5,%6,%7}, {%8,%9}, {%0,%1,%2,%3};"
                 : "+f"(d[0]), "+f"(d[1]), "+f"(d[2]), "+f"(d[3])
                 : "r"(a[0]), "r"(a[1]), "r"(a[2]), "r"(a[3]),
                   "r"(b0), "r"(b1));
}
#define CP_ASYNC(dst, src) \
    asm volatile("cp.async.cg.shared.global [%0], [%1], 16;" \
                 :: "r"(dst), "l"(src) : "memory")
#define CP_COMMIT() asm volatile("cp.async.commit_group;" ::: "memory")
#define CP_WAIT1()  asm volatile("cp.async.wait_group 1;" ::: "memory")

// ---------------- zero scratch ----------------
__global__ void zero_kernel() {
    int i = blockIdx.x * blockDim.x + threadIdx.x;
    if (i < G * NCH * NCH) (&g_S2[0][0][0])[i] = 0.0f;
    if (i < G * NCH)       (&g_sum[0][0])[i]   = 0.0f;
}

// ---------------- phase 1: covariance (unchanged from R15, occ-4) ----------
__global__ __launch_bounds__(256, 4) void cov_kernel(const float* __restrict__ x) {
    extern __shared__ float smf[];
    const int gi  = blockIdx.x / NBLKC;
    const int blk = blockIdx.x % NBLKC;
    const int tid = threadIdx.x, w = tid >> 5, lane = tid & 31;
    const int g = lane >> 2, t4 = lane & 3;

    int r0, c0, kbase, nkk, diag;
    if (w < 2)      { r0 = 0;  c0 = 0;  kbase = (w & 1) * 4;  nkk = 4; diag = 1; }
    else if (w < 6) { r0 = 0;  c0 = 32; kbase = (w - 2) * 2;  nkk = 2; diag = 0; }
    else            { r0 = 32; c0 = 32; kbase = (w & 1) * 4;  nkk = 4; diag = 1; }
    const bool sumduty = (w >= 2) && (w < 6);
    const int sch_ch   = (tid - 64) >> 1;
    const int sch_half = tid & 1;

    const int lc = tid >> 4, s4 = (tid & 15) * 4;
    const uint32_t sb = smem_u32(smf);
    const float* xg = x + (size_t)gi * NCH * HWX;
    const int ntile = (CTILESC - blk + NBLKC - 1) / NBLKC;

    auto issue = [&](int idx) {
        if (idx < ntile) {
            const int t = blk + idx * NBLKC;
            const int b = t / CCH, hw0 = (t % CCH) * CTC;
            const uint32_t dst0 = sb + (uint32_t)((idx & 1) * NCH * CPC + lc * CPC + s4) * 4;
            #pragma unroll
            for (int i = 0; i < 4; i++) {
                const float* src = xg + (size_t)(b * CC + lc + 16 * i) * HWX + hw0 + s4;
                CP_ASYNC(dst0 + (uint32_t)(16 * i * CPC) * 4, src);
            }
        }
        CP_COMMIT();
    };

    float acc[32];
    #pragma unroll
    for (int i = 0; i < 32; i++) acc[i] = 0.0f;
    float sch = 0.0f;

    issue(0);
    for (int it = 0; it < ntile; ++it) {
        __syncthreads();
        issue(it + 1);
        CP_WAIT1();
        __syncthreads();

        const float* tb = smf + (it & 1) * NCH * CPC;
        if (sumduty) {
            #pragma unroll
            for (int i = 0; i < 8; i++) {
                const int slot = 8 * sch_half + ((i + 4 * sch_half) & 7);
                float4 v = *(const float4*)(tb + sch_ch * CPC + slot * 4);
                sch += (v.x + v.y) + (v.z + v.w);
            }
        }
        const uint32_t* tu = (const uint32_t*)tb;
        #pragma unroll
        for (int kk = 0; kk < 4; kk++) {
            if (kk < nkk) {
                const int k0 = (kbase + kk) * 8;
                uint32_t a0[4], a1[4];
                a0[0] = tu[(r0 + g) * CPC + k0 + t4];
                a0[1] = tu[(r0 + g + 8) * CPC + k0 + t4];
                a0[2] = tu[(r0 + g) * CPC + k0 + t4 + 4];
                a0[3] = tu[(r0 + g + 8) * CPC + k0 + t4 + 4];
                a1[0] = tu[(r0 + 16 + g) * CPC + k0 + t4];
                a1[1] = tu[(r0 + 24 + g) * CPC + k0 + t4];
                a1[2] = tu[(r0 + 16 + g) * CPC + k0 + t4 + 4];
                a1[3] = tu[(r0 + 24 + g) * CPC + k0 + t4 + 4];
                if (diag) {
                    const uint32_t bv[4][2] = {
                        {a0[0], a0[2]}, {a0[1], a0[3]},
                        {a1[0], a1[2]}, {a1[1], a1[3]} };
                    #pragma unroll
                    for (int j = 0; j < 4; j++) {
                        mma8(acc + j * 4,      a0, bv[j][0], bv[j][1]);
                        mma8(acc + 16 + j * 4, a1, bv[j][0], bv[j][1]);
                    }
                } else {
                    #pragma unroll
                    for (int j = 0; j < 4; j++) {
                        const int n0 = c0 + j * 8 + g;
                        const uint32_t b0 = tu[n0 * CPC + k0 + t4];
                        const uint32_t b1 = tu[n0 * CPC + k0 + t4 + 4];
                        mma8(acc + j * 4,      a0, b0, b1);
                        mma8(acc + 16 + j * 4, a1, b0, b1);
                    }
                }
            }
        }
    }

    __syncthreads();
    const int q = (c0 == 0) ? 0 : ((r0 == 0) ? 1 : 2);
    float* qa = smf + q * (32 * RPITCH);

    auto dump = [&](bool add) {
        #pragma unroll
        for (int mh = 0; mh < 2; mh++) {
            #pragma unroll
            for (int j = 0; j < 4; j++) {
                const int lr0 = mh * 16 + g, lc0 = j * 8 + 2 * t4;
                float* p0 = qa + lr0 * RPITCH + lc0;
                float* p1 = qa + (lr0 + 8) * RPITCH + lc0;
                if (add) {
                    p0[0] += acc[mh*16 + j*4 + 0]; p0[1] += acc[mh*16 + j*4 + 1];
                    p1[0] += acc[mh*16 + j*4 + 2]; p1[1] += acc[mh*16 + j*4 + 3];
                } else {
                    p0[0] = acc[mh*16 + j*4 + 0];  p0[1] = acc[mh*16 + j*4 + 1];
                    p1[0] = acc[mh*16 + j*4 + 2];  p1[1] = acc[mh*16 + j*4 + 3];
                }
            }
        }
    };
    if (w == 0 || w == 2 || w == 6) dump(false);
    __syncthreads();
    if (w == 1 || w == 3 || w == 7) dump(true);
    __syncthreads();
    if (w == 4) dump(true);
    __syncthreads();
    if (w == 5) dump(true);
    __syncthreads();

    for (int i = tid; i < 3072; i += 256) {
        const int qq = i >> 10, cell = i & 1023;
        const int lr = cell >> 5, lcq = cell & 31;
        const int rr = ((qq == 2) ? 32 : 0) + lr;
        const int cc = ((qq == 0) ? 0 : 32) + lcq;
        atomicAdd(&g_S2[gi][rr][cc], smf[qq * (32 * RPITCH) + lr * RPITCH + lcq]);
    }
    if (sumduty) {
        sch += __shfl_xor_sync(0xffffffffu, sch, 1);
        if (sch_half == 0) atomicAdd(&g_sum[gi][sch_ch], sch);
    }
}

// ---------------- phase 2: Newton-Schulz via HMMA hi/lo, 512 threads -------
__device__ __forceinline__ void mm64h(float* O, const float* A, const float* B) {
    const int w = threadIdx.x >> 5, lane = threadIdx.x & 31;
    const int g = lane >> 2, t4 = lane & 3;
    const int r0 = (w >> 2) * 16, c0 = (w & 3) * 16;
    float acc[8];
    #pragma unroll
    for (int i = 0; i < 8; i++) acc[i] = 0.0f;
    #pragma unroll
    for (int kk = 0; kk < 8; kk++) {
        const int k0 = kk * 8;
        float av[4];
        av[0] = A[(r0 + g) * NSP + k0 + t4];
        av[1] = A[(r0 + g + 8) * NSP + k0 + t4];
        av[2] = A[(r0 + g) * NSP + k0 + t4 + 4];
        av[3] = A[(r0 + g + 8) * NSP + k0 + t4 + 4];
        uint32_t ah[4], al[4];
        #pragma unroll
        for (int i = 0; i < 4; i++) {
            ah[i] = tf32r(av[i]);
            al[i] = tf32r(av[i] - __uint_as_float(ah[i]));
        }
        #pragma unroll
        for (int j = 0; j < 2; j++) {
            const int n0 = c0 + j * 8 + g;
            const float b0f = B[(k0 + t4) * NSP + n0];
            const float b1f = B[(k0 + t4 + 4) * NSP + n0];
            const uint32_t bh0 = tf32r(b0f);
            const uint32_t bl0 = tf32r(b0f - __uint_as_float(bh0));
            const uint32_t bh1 = tf32r(b1f);
            const uint32_t bl1 = tf32r(b1f - __uint_as_float(bh1));
            mma8(acc + j * 4, ah, bh0, bh1);
            mma8(acc + j * 4, ah, bl0, bl1);
            mma8(acc + j * 4, al, bh0, bh1);
        }
    }
    #pragma unroll
    for (int j = 0; j < 2; j++) {
        const int col = c0 + j * 8 + 2 * t4;
        *(float2*)(O + (r0 + g) * NSP + col)     = make_float2(acc[j*4+0], acc[j*4+1]);
        *(float2*)(O + (r0 + g + 8) * NSP + col) = make_float2(acc[j*4+2], acc[j*4+3]);
    }
    __syncthreads();
}

__global__ __launch_bounds__(512) void ns_kernel(const float* __restrict__ weight,
                                                 const float* __restrict__ bias) {
    extern __shared__ float sm[];
    float* Sn = sm;                 float* Pm = sm + NCH * NSP;
    float* T1 = sm + 2 * NCH * NSP; float* T2 = sm + 3 * NCH * NSP;
    float* mean = sm + 4 * NCH * NSP;   // 64
    float* misc = mean + 64;
    const int gi = blockIdx.x, tid = threadIdx.x;
    const int r = tid >> 3, cb = (tid & 7) << 3;

    if (tid < 64) mean[tid] = g_sum[gi][tid] * (1.0f / MTOT);
    __syncthreads();
    #pragma unroll
    for (int j = 0; j < 8; j++) {
        int c = cb + j;
        float s2v = (r >= 32 && c < 32) ? g_S2[gi][c][r] : g_S2[gi][r][c];
        float sig = s2v * (1.0f / MTOT) - mean[r] * mean[c];
        if (r == c) sig += EPSV;
        Sn[r * NSP + c] = sig;
    }
    __syncthreads();
    if (tid < 32) {
        float ts = Sn[tid * NSP + tid] + Sn[(tid + 32) * NSP + (tid + 32)];
        #pragma unroll
        for (int o = 16; o; o >>= 1) ts += __shfl_xor_sync(0xffffffffu, ts, o);
        if (tid == 0) misc[0] = 1.0f / ts;
    }
    __syncthreads();
    const float rTr = misc[0];
    #pragma unroll
    for (int j = 0; j < 8; j++) {
        int c = cb + j;
        Sn[r * NSP + c] *= rTr;
        Pm[r * NSP + c] = (r == c) ? 1.0f : 0.0f;
    }
    __syncthreads();
    for (int it = 0; it < NS_T; it++) {
        mm64h(T1, Pm, Pm);    // P^2
        mm64h(T2, T1, Pm);    // P^3
        mm64h(T1, T2, Sn);    // P^3 Sn
        #pragma unroll
        for (int j = 0; j < 8; j++) {
            int idx = r * NSP + cb + j;
            Pm[idx] = 1.5f * Pm[idx] - 0.5f * T1[idx];
        }
        __syncthreads();
    }
    const float s = sqrtf(rTr);
    #pragma unroll
    for (int j = 0; j < 8; j++) {
        int d = cb + j;
        g_wm[gi][r][d] = Pm[r * NSP + d] * s * weight[gi * NCH + r];
    }
    if (tid < 64) {
        float off = 0.0f;
        for (int d = 0; d < 64; d++) off += Pm[tid * NSP + d] * mean[d];
        g_beta[gi][tid] = bias[gi * NCH + tid] - weight[gi * NCH + tid] * s * off;
    }
}

// ---------------- phase 3: whitening apply (occ-3, 64x64 tiles) -------------
// 8 warps = 4 row-strips (16ch) x 2 col-strips (32 samples). afr halved to
// 32 regs -> fits 84-reg cap at 3 CTAs/SM. 49 tiles/image exact (no half).
__global__ __launch_bounds__(256, 3) void whiten_kernel(const float* __restrict__ x,
                                                        float* __restrict__ out) {
    extern __shared__ float smf[];
    const int gi  = blockIdx.x / NBLKW;
    const int blk = blockIdx.x % NBLKW;
    const int tid = threadIdx.x, w = tid >> 5, lane = tid & 31;
    const int g = lane >> 2, t4 = lane & 3;
    const int r0 = (w >> 1) * 16, nt = w & 1;
    const int lc = tid >> 4, s4 = (tid & 15) * 4;   // copy map: 4 rows/thread
    const uint32_t sb = smem_u32(smf);
    const float* xg = x + (size_t)gi * NCH * HWX;
    float* og = out + (size_t)gi * NCH * HWX;
    const int ntile = (WTILES2 - blk + NBLKW - 1) / NBLKW;

    // hoist wm A-fragments (16 output rows) + beta
    uint32_t afr[8][4];
    #pragma unroll
    for (int kk = 0; kk < 8; kk++) {
        const int k0 = kk * 8;
        afr[kk][0] = tf32r(g_wm[gi][r0 + g][k0 + t4]);
        afr[kk][1] = tf32r(g_wm[gi][r0 + g + 8][k0 + t4]);
        afr[kk][2] = tf32r(g_wm[gi][r0 + g][k0 + t4 + 4]);
        afr[kk][3] = tf32r(g_wm[gi][r0 + g + 8][k0 + t4 + 4]);
    }
    const float bet0 = g_beta[gi][r0 + g];
    const float bet1 = g_beta[gi][r0 + g + 8];

    auto issue = [&](int idx) {
        if (idx < ntile) {
            const int t = blk + idx * NBLKW;
            const int b = t / WCH, hw0 = (t % WCH) * WTC;
            const uint32_t dst0 = sb + (uint32_t)((idx & 1) * NCH * WP2 + lc * WP2 + s4) * 4;
            #pragma unroll
            for (int i = 0; i < 4; i++) {
                const float* src = xg + (size_t)(b * CC + lc + 16 * i) * HWX + hw0 + s4;
                CP_ASYNC(dst0 + (uint32_t)(16 * i * WP2) * 4, src);
            }
        }
        CP_COMMIT();
    };

    issue(0);
    for (int it = 0; it < ntile; ++it) {
        __syncthreads();
        issue(it + 1);
        CP_WAIT1();
        __syncthreads();

        const int t = blk + it * NBLKW;
        const int b = t / WCH, hw0 = (t % WCH) * WTC;
        const uint32_t* tu = (const uint32_t*)(smf + (it & 1) * NCH * WP2);

        float acc[16];
        #pragma unroll
        for (int i = 0; i < 16; i++) acc[i] = 0.0f;
        #pragma unroll
        for (int kk = 0; kk < 8; kk++) {
            const int k0 = kk * 8;
            #pragma unroll
            for (int j = 0; j < 4; j++) {
                const int n0 = nt * 32 + j * 8 + g;
                const uint32_t b0 = tu[(k0 + t4) * WP2 + n0];
                const uint32_t b1 = tu[(k0 + t4 + 4) * WP2 + n0];
                mma8(acc + j * 4, afr[kk], b0, b1);
            }
        }
        #pragma unroll
        for (int j = 0; j < 4; j++) {
            const int col = nt * 32 + j * 8 + 2 * t4;
            float* o0 = og + ((size_t)b * CC + r0 + g) * HWX + hw0 + col;
            *(float2*)o0 = make_float2(acc[j*4+0] + bet0, acc[j*4+1] + bet0);
            *(float2*)(o0 + (size_t)8 * HWX) =
                make_float2(acc[j*4+2] + bet1, acc[j*4+3] + bet1);
        }
    }
}

// ---------------- launch ----------------
extern "C" void kernel_launch(void* const* d_in, const int* in_sizes, int n_in,
                              void* d_out, int out_size) {
    const float* x      = (const float*)d_in[0];
    const float* weight = (const float*)d_in[1];
    const float* bias   = (const float*)d_in[2];
    float* out          = (float*)d_out;

    const int NS_SMEM  = (4 * NCH * NSP + 64 + 16) * 4;   // 74048
    const int COV_SMEM = 2 * NCH * CPC * 4;               // 34816 (x4 = 139KB)
    const int WHT_SMEM = 2 * NCH * WP2 * 4;               // 36864 (x3 = 111KB)
    cudaFuncSetAttribute(ns_kernel,     cudaFuncAttributeMaxDynamicSharedMemorySize, NS_SMEM);
    cudaFuncSetAttribute(cov_kernel,    cudaFuncAttributeMaxDynamicSharedMemorySize, COV_SMEM);
    cudaFuncSetAttribute(whiten_kernel, cudaFuncAttributeMaxDynamicSharedMemorySize, WHT_SMEM);

    zero_kernel<<<(G * NCH * NCH + 255) / 256, 256>>>();
    cov_kernel<<<G * NBLKC, 256, COV_SMEM>>>(x);
    ns_kernel<<<G, 512, NS_SMEM>>>(weight, bias);
    whiten_kernel<<<G * NBLKW, 256, WHT_SMEM>>>(x, out);
}

// round 17
// speedup vs baseline: 1.0125x; 1.0125x over previous
#include <cuda_runtime.h>
#include <cstdint>

// ---------------- problem constants ----------------
#define BB      64
#define CC      256
#define HWX     3136        // 56*56
#define G       4
#define NCH     64
#define MTOT    (BB*HWX)
#define EPSV    1e-5f
#define NS_T    5
#define NSP     72          // ns matrix pitch (conflict-free frag loads)

// cov tiling: 64-sample tiles (49/image exact), 2-stage, 4 CTAs/SM (R15)
#define CTC     64
#define CCH     49           // chunks per image
#define CTILESC (BB*CCH)     // 3136 per group
#define NBLKC   148          // cov blocks per group (grid 592 = 4/SM)
#define CPC     68           // pitch%32==4 -> conflict-free frag loads
#define RPITCH  33           // reduction-area pitch

// whiten tiling: 64-sample tiles, 2-stage, 3 CTAs/SM, REVERSE traversal
#define WTC     64
#define WCH     49
#define WTILES2 (BB*WCH)     // 3136 per group
#define NBLKW   111          // whiten blocks per group (grid 444 = 3/SM)
#define WP2     72           // pitch%32==8 -> B-read banks 8*t4+g distinct

// ---------------- device scratch ----------------
__device__ float g_S2[G][NCH][NCH];
__device__ float g_sum[G][NCH];
__device__ float g_wm[G][NCH][NCH];   // [g][c][d], weight+sqrt(rTr) folded in
__device__ float g_beta[G][NCH];

// ---------------- helpers ----------------
__device__ __forceinline__ uint32_t tf32r(float f) {
    uint32_t r; asm("cvt.rn.tf32.f32 %0, %1;" : "=r"(r) : "f"(f)); return r;
}
__device__ __forceinline__ uint32_t smem_u32(const void* p) {
    uint32_t a;
    asm("{ .reg .u64 t; cvta.to.shared.u64 t, %1; cvt.u32.u64 %0, t; }"
        : "=r"(a) : "l"(p));
    return a;
}
__device__ __forceinline__ void mma8(float* d, const uint32_t* a,
                                     uint32_t b0, uint32_t b1) {
    asm volatile("mma.sync.aligned.m16n8k8.row.col.f32.tf32.tf32.f32 "
                 "{%0,%1,%2,%3}, {%4,%5,%6,%7}, {%8,%9}, {%0,%1,%2,%3};"
                 : "+f"(d[0]), "+f"(d[1]), "+f"(d[2]), "+f"(d[3])
                 : "r"(a[0]), "r"(a[1]), "r"(a[2]), "r"(a[3]),
                   "r"(b0), "r"(b1));
}
#define CP_ASYNC(dst, src) \
    asm volatile("cp.async.cg.shared.global [%0], [%1], 16;" \
                 :: "r"(dst), "l"(src) : "memory")
#define CP_COMMIT() asm volatile("cp.async.commit_group;" ::: "memory")
#define CP_WAIT1()  asm volatile("cp.async.wait_group 1;" ::: "memory")

// ---------------- zero scratch ----------------
__global__ void zero_kernel() {
    int i = blockIdx.x * blockDim.x + threadIdx.x;
    if (i < G * NCH * NCH) (&g_S2[0][0][0])[i] = 0.0f;
    if (i < G * NCH)       (&g_sum[0][0])[i]   = 0.0f;
}

// ---------------- phase 1: covariance (unchanged from R15, occ-4) ----------
__global__ __launch_bounds__(256, 4) void cov_kernel(const float* __restrict__ x) {
    extern __shared__ float smf[];
    const int gi  = blockIdx.x / NBLKC;
    const int blk = blockIdx.x % NBLKC;
    const int tid = threadIdx.x, w = tid >> 5, lane = tid & 31;
    const int g = lane >> 2, t4 = lane & 3;

    int r0, c0, kbase, nkk, diag;
    if (w < 2)      { r0 = 0;  c0 = 0;  kbase = (w & 1) * 4;  nkk = 4; diag = 1; }
    else if (w < 6) { r0 = 0;  c0 = 32; kbase = (w - 2) * 2;  nkk = 2; diag = 0; }
    else            { r0 = 32; c0 = 32; kbase = (w & 1) * 4;  nkk = 4; diag = 1; }
    const bool sumduty = (w >= 2) && (w < 6);
    const int sch_ch   = (tid - 64) >> 1;
    const int sch_half = tid & 1;

    const int lc = tid >> 4, s4 = (tid & 15) * 4;
    const uint32_t sb = smem_u32(smf);
    const float* xg = x + (size_t)gi * NCH * HWX;
    const int ntile = (CTILESC - blk + NBLKC - 1) / NBLKC;

    auto issue = [&](int idx) {
        if (idx < ntile) {
            const int t = blk + idx * NBLKC;
            const int b = t / CCH, hw0 = (t % CCH) * CTC;
            const uint32_t dst0 = sb + (uint32_t)((idx & 1) * NCH * CPC + lc * CPC + s4) * 4;
            #pragma unroll
            for (int i = 0; i < 4; i++) {
                const float* src = xg + (size_t)(b * CC + lc + 16 * i) * HWX + hw0 + s4;
                CP_ASYNC(dst0 + (uint32_t)(16 * i * CPC) * 4, src);
            }
        }
        CP_COMMIT();
    };

    float acc[32];
    #pragma unroll
    for (int i = 0; i < 32; i++) acc[i] = 0.0f;
    float sch = 0.0f;

    issue(0);
    for (int it = 0; it < ntile; ++it) {
        __syncthreads();
        issue(it + 1);
        CP_WAIT1();
        __syncthreads();

        const float* tb = smf + (it & 1) * NCH * CPC;
        if (sumduty) {
            #pragma unroll
            for (int i = 0; i < 8; i++) {
                const int slot = 8 * sch_half + ((i + 4 * sch_half) & 7);
                float4 v = *(const float4*)(tb + sch_ch * CPC + slot * 4);
                sch += (v.x + v.y) + (v.z + v.w);
            }
        }
        const uint32_t* tu = (const uint32_t*)tb;
        #pragma unroll
        for (int kk = 0; kk < 4; kk++) {
            if (kk < nkk) {
                const int k0 = (kbase + kk) * 8;
                uint32_t a0[4], a1[4];
                a0[0] = tu[(r0 + g) * CPC + k0 + t4];
                a0[1] = tu[(r0 + g + 8) * CPC + k0 + t4];
                a0[2] = tu[(r0 + g) * CPC + k0 + t4 + 4];
                a0[3] = tu[(r0 + g + 8) * CPC + k0 + t4 + 4];
                a1[0] = tu[(r0 + 16 + g) * CPC + k0 + t4];
                a1[1] = tu[(r0 + 24 + g) * CPC + k0 + t4];
                a1[2] = tu[(r0 + 16 + g) * CPC + k0 + t4 + 4];
                a1[3] = tu[(r0 + 24 + g) * CPC + k0 + t4 + 4];
                if (diag) {
                    const uint32_t bv[4][2] = {
                        {a0[0], a0[2]}, {a0[1], a0[3]},
                        {a1[0], a1[2]}, {a1[1], a1[3]} };
                    #pragma unroll
                    for (int j = 0; j < 4; j++) {
                        mma8(acc + j * 4,      a0, bv[j][0], bv[j][1]);
                        mma8(acc + 16 + j * 4, a1, bv[j][0], bv[j][1]);
                    }
                } else {
                    #pragma unroll
                    for (int j = 0; j < 4; j++) {
                        const int n0 = c0 + j * 8 + g;
                        const uint32_t b0 = tu[n0 * CPC + k0 + t4];
                        const uint32_t b1 = tu[n0 * CPC + k0 + t4 + 4];
                        mma8(acc + j * 4,      a0, b0, b1);
                        mma8(acc + 16 + j * 4, a1, b0, b1);
                    }
                }
            }
        }
    }

    __syncthreads();
    const int q = (c0 == 0) ? 0 : ((r0 == 0) ? 1 : 2);
    float* qa = smf + q * (32 * RPITCH);

    auto dump = [&](bool add) {
        #pragma unroll
        for (int mh = 0; mh < 2; mh++) {
            #pragma unroll
            for (int j = 0; j < 4; j++) {
                const int lr0 = mh * 16 + g, lc0 = j * 8 + 2 * t4;
                float* p0 = qa + lr0 * RPITCH + lc0;
                float* p1 = qa + (lr0 + 8) * RPITCH + lc0;
                if (add) {
                    p0[0] += acc[mh*16 + j*4 + 0]; p0[1] += acc[mh*16 + j*4 + 1];
                    p1[0] += acc[mh*16 + j*4 + 2]; p1[1] += acc[mh*16 + j*4 + 3];
                } else {
                    p0[0] = acc[mh*16 + j*4 + 0];  p0[1] = acc[mh*16 + j*4 + 1];
                    p1[0] = acc[mh*16 + j*4 + 2];  p1[1] = acc[mh*16 + j*4 + 3];
                }
            }
        }
    };
    if (w == 0 || w == 2 || w == 6) dump(false);
    __syncthreads();
    if (w == 1 || w == 3 || w == 7) dump(true);
    __syncthreads();
    if (w == 4) dump(true);
    __syncthreads();
    if (w == 5) dump(true);
    __syncthreads();

    for (int i = tid; i < 3072; i += 256) {
        const int qq = i >> 10, cell = i & 1023;
        const int lr = cell >> 5, lcq = cell & 31;
        const int rr = ((qq == 2) ? 32 : 0) + lr;
        const int cc = ((qq == 0) ? 0 : 32) + lcq;
        atomicAdd(&g_S2[gi][rr][cc], smf[qq * (32 * RPITCH) + lr * RPITCH + lcq]);
    }
    if (sumduty) {
        sch += __shfl_xor_sync(0xffffffffu, sch, 1);
        if (sch_half == 0) atomicAdd(&g_sum[gi][sch_ch], sch);
    }
}

// ---------------- phase 2: Newton-Schulz via HMMA hi/lo, 512 threads -------
__device__ __forceinline__ void mm64h(float* O, const float* A, const float* B) {
    const int w = threadIdx.x >> 5, lane = threadIdx.x & 31;
    const int g = lane >> 2, t4 = lane & 3;
    const int r0 = (w >> 2) * 16, c0 = (w & 3) * 16;
    float acc[8];
    #pragma unroll
    for (int i = 0; i < 8; i++) acc[i] = 0.0f;
    #pragma unroll
    for (int kk = 0; kk < 8; kk++) {
        const int k0 = kk * 8;
        float av[4];
        av[0] = A[(r0 + g) * NSP + k0 + t4];
        av[1] = A[(r0 + g + 8) * NSP + k0 + t4];
        av[2] = A[(r0 + g) * NSP + k0 + t4 + 4];
        av[3] = A[(r0 + g + 8) * NSP + k0 + t4 + 4];
        uint32_t ah[4], al[4];
        #pragma unroll
        for (int i = 0; i < 4; i++) {
            ah[i] = tf32r(av[i]);
            al[i] = tf32r(av[i] - __uint_as_float(ah[i]));
        }
        #pragma unroll
        for (int j = 0; j < 2; j++) {
            const int n0 = c0 + j * 8 + g;
            const float b0f = B[(k0 + t4) * NSP + n0];
            const float b1f = B[(k0 + t4 + 4) * NSP + n0];
            const uint32_t bh0 = tf32r(b0f);
            const uint32_t bl0 = tf32r(b0f - __uint_as_float(bh0));
            const uint32_t bh1 = tf32r(b1f);
            const uint32_t bl1 = tf32r(b1f - __uint_as_float(bh1));
            mma8(acc + j * 4, ah, bh0, bh1);
            mma8(acc + j * 4, ah, bl0, bl1);
            mma8(acc + j * 4, al, bh0, bh1);
        }
    }
    #pragma unroll
    for (int j = 0; j < 2; j++) {
        const int col = c0 + j * 8 + 2 * t4;
        *(float2*)(O + (r0 + g) * NSP + col)     = make_float2(acc[j*4+0], acc[j*4+1]);
        *(float2*)(O + (r0 + g + 8) * NSP + col) = make_float2(acc[j*4+2], acc[j*4+3]);
    }
    __syncthreads();
}

__global__ __launch_bounds__(512) void ns_kernel(const float* __restrict__ weight,
                                                 const float* __restrict__ bias) {
    extern __shared__ float sm[];
    float* Sn = sm;                 float* Pm = sm + NCH * NSP;
    float* T1 = sm + 2 * NCH * NSP; float* T2 = sm + 3 * NCH * NSP;
    float* mean = sm + 4 * NCH * NSP;   // 64
    float* misc = mean + 64;
    const int gi = blockIdx.x, tid = threadIdx.x;
    const int r = tid >> 3, cb = (tid & 7) << 3;

    if (tid < 64) mean[tid] = g_sum[gi][tid] * (1.0f / MTOT);
    __syncthreads();
    #pragma unroll
    for (int j = 0; j < 8; j++) {
        int c = cb + j;
        float s2v = (r >= 32 && c < 32) ? g_S2[gi][c][r] : g_S2[gi][r][c];
        float sig = s2v * (1.0f / MTOT) - mean[r] * mean[c];
        if (r == c) sig += EPSV;
        Sn[r * NSP + c] = sig;
    }
    __syncthreads();
    if (tid < 32) {
        float ts = Sn[tid * NSP + tid] + Sn[(tid + 32) * NSP + (tid + 32)];
        #pragma unroll
        for (int o = 16; o; o >>= 1) ts += __shfl_xor_sync(0xffffffffu, ts, o);
        if (tid == 0) misc[0] = 1.0f / ts;
    }
    __syncthreads();
    const float rTr = misc[0];
    #pragma unroll
    for (int j = 0; j < 8; j++) {
        int c = cb + j;
        Sn[r * NSP + c] *= rTr;
        Pm[r * NSP + c] = (r == c) ? 1.0f : 0.0f;
    }
    __syncthreads();
    for (int it = 0; it < NS_T; it++) {
        mm64h(T1, Pm, Pm);    // P^2
        mm64h(T2, T1, Pm);    // P^3
        mm64h(T1, T2, Sn);    // P^3 Sn
        #pragma unroll
        for (int j = 0; j < 8; j++) {
            int idx = r * NSP + cb + j;
            Pm[idx] = 1.5f * Pm[idx] - 0.5f * T1[idx];
        }
        __syncthreads();
    }
    const float s = sqrtf(rTr);
    #pragma unroll
    for (int j = 0; j < 8; j++) {
        int d = cb + j;
        g_wm[gi][r][d] = Pm[r * NSP + d] * s * weight[gi * NCH + r];
    }
    if (tid < 64) {
        float off = 0.0f;
        for (int d = 0; d < 64; d++) off += Pm[tid * NSP + d] * mean[d];
        g_beta[gi][tid] = bias[gi * NCH + tid] - weight[gi * NCH + tid] * s * off;
    }
}

// ---------------- phase 3: whitening apply (occ-3, REVERSE traversal) -------
// Walks tiles high->low so its first reads hit the x-range cov streamed last
// (still resident in L2). Otherwise identical to R16.
__global__ __launch_bounds__(256, 3) void whiten_kernel(const float* __restrict__ x,
                                                        float* __restrict__ out) {
    extern __shared__ float smf[];
    const int gi  = blockIdx.x / NBLKW;
    const int blk = blockIdx.x % NBLKW;
    const int tid = threadIdx.x, w = tid >> 5, lane = tid & 31;
    const int g = lane >> 2, t4 = lane & 3;
    const int r0 = (w >> 1) * 16, nt = w & 1;
    const int lc = tid >> 4, s4 = (tid & 15) * 4;
    const uint32_t sb = smem_u32(smf);
    const float* xg = x + (size_t)gi * NCH * HWX;
    float* og = out + (size_t)gi * NCH * HWX;
    const int ntile = (WTILES2 - blk + NBLKW - 1) / NBLKW;

    uint32_t afr[8][4];
    #pragma unroll
    for (int kk = 0; kk < 8; kk++) {
        const int k0 = kk * 8;
        afr[kk][0] = tf32r(g_wm[gi][r0 + g][k0 + t4]);
        afr[kk][1] = tf32r(g_wm[gi][r0 + g + 8][k0 + t4]);
        afr[kk][2] = tf32r(g_wm[gi][r0 + g][k0 + t4 + 4]);
        afr[kk][3] = tf32r(g_wm[gi][r0 + g + 8][k0 + t4 + 4]);
    }
    const float bet0 = g_beta[gi][r0 + g];
    const float bet1 = g_beta[gi][r0 + g + 8];

    auto issue = [&](int idx) {
        if (idx < ntile) {
            const int t = (WTILES2 - 1) - (blk + idx * NBLKW);   // reverse
            const int b = t / WCH, hw0 = (t % WCH) * WTC;
            const uint32_t dst0 = sb + (uint32_t)((idx & 1) * NCH * WP2 + lc * WP2 + s4) * 4;
            #pragma unroll
            for (int i = 0; i < 4; i++) {
                const float* src = xg + (size_t)(b * CC + lc + 16 * i) * HWX + hw0 + s4;
                CP_ASYNC(dst0 + (uint32_t)(16 * i * WP2) * 4, src);
            }
        }
        CP_COMMIT();
    };

    issue(0);
    for (int it = 0; it < ntile; ++it) {
        __syncthreads();
        issue(it + 1);
        CP_WAIT1();
        __syncthreads();

        const int t = (WTILES2 - 1) - (blk + it * NBLKW);        // reverse
        const int b = t / WCH, hw0 = (t % WCH) * WTC;
        const uint32_t* tu = (const uint32_t*)(smf + (it & 1) * NCH * WP2);

        float acc[16];
        #pragma unroll
        for (int i = 0; i < 16; i++) acc[i] = 0.0f;
        #pragma unroll
        for (int kk = 0; kk < 8; kk++) {
            const int k0 = kk * 8;
            #pragma unroll
            for (int j = 0; j < 4; j++) {
                const int n0 = nt * 32 + j * 8 + g;
                const uint32_t b0 = tu[(k0 + t4) * WP2 + n0];
                const uint32_t b1 = tu[(k0 + t4 + 4) * WP2 + n0];
                mma8(acc + j * 4, afr[kk], b0, b1);
            }
        }
        #pragma unroll
        for (int j = 0; j < 4; j++) {
            const int col = nt * 32 + j * 8 + 2 * t4;
            float* o0 = og + ((size_t)b * CC + r0 + g) * HWX + hw0 + col;
            *(float2*)o0 = make_float2(acc[j*4+0] + bet0, acc[j*4+1] + bet0);
            *(float2*)(o0 + (size_t)8 * HWX) =
                make_float2(acc[j*4+2] + bet1, acc[j*4+3] + bet1);
        }
    }
}

// ---------------- launch ----------------
extern "C" void kernel_launch(void* const* d_in, const int* in_sizes, int n_in,
                              void* d_out, int out_size) {
    const float* x      = (const float*)d_in[0];
    const float* weight = (const float*)d_in[1];
    const float* bias   = (const float*)d_in[2];
    float* out          = (float*)d_out;

    const int NS_SMEM  = (4 * NCH * NSP + 64 + 16) * 4;   // 74048
    const int COV_SMEM = 2 * NCH * CPC * 4;               // 34816 (x4 = 139KB)
    const int WHT_SMEM = 2 * NCH * WP2 * 4;               // 36864 (x3 = 111KB)
    cudaFuncSetAttribute(ns_kernel,     cudaFuncAttributeMaxDynamicSharedMemorySize, NS_SMEM);
    cudaFuncSetAttribute(cov_kernel,    cudaFuncAttributeMaxDynamicSharedMemorySize, COV_SMEM);
    cudaFuncSetAttribute(whiten_kernel, cudaFuncAttributeMaxDynamicSharedMemorySize, WHT_SMEM);

    zero_kernel<<<(G * NCH * NCH + 255) / 256, 256>>>();
    cov_kernel<<<G * NBLKC, 256, COV_SMEM>>>(x);
    ns_kernel<<<G, 512, NS_SMEM>>>(weight, bias);
    whiten_kernel<<<G * NBLKW, 256, WHT_SMEM>>>(x, out);
}